// round 14
// baseline (speedup 1.0000x reference)
#include <cuda_runtime.h>
#include <cuda_bf16.h>

typedef unsigned int u32;
typedef unsigned long long u64;
typedef unsigned char u8;

#define BATCH 16384
#define NOUT  128
#define LH    64
#define NPRED 25

// ---------------- scratch ----------------
__device__ float g_A1[BATCH * 32];
__device__ float g_A2[BATCH * 32];
__device__ float g_m [BATCH * LH];
__device__ float g_part1[128 * 64];
__device__ float g_part2[128 * 64];
// bf16-split, gate-interleaved (n = 4q+gate), swizzled weights: 256 n-rows x 128 k
__device__ u8 g_Wih_sw[65536];
__device__ u8 g_Wc_sw [65536];

// ---------------- helpers ----------------
__device__ __forceinline__ u64 pk2(float a, float b) {
    u64 r; asm("mov.b64 %0,{%1,%2};" : "=l"(r) : "f"(a), "f"(b)); return r;
}
__device__ __forceinline__ void upk2(u64 v, float &a, float &b) {
    asm("mov.b64 {%0,%1},%2;" : "=f"(a), "=f"(b) : "l"(v));
}
__device__ __forceinline__ void ffma2(u64 &d, u64 a, u64 b) {
    asm("fma.rn.f32x2 %0,%1,%2,%0;" : "+l"(d) : "l"(a), "l"(b));
}
__device__ __forceinline__ float tanhfast(float x) {
    float r; asm("tanh.approx.f32 %0,%1;" : "=f"(r) : "f"(x)); return r;
}
__device__ __forceinline__ u32 smem_u32(const void* p) {
    u32 a; asm("{ .reg .u64 t; cvta.to.shared.u64 t, %1; cvt.u32.u64 %0, t; }"
               : "=r"(a) : "l"(p));
    return a;
}
// butterfly-combine a packed f32x2 accumulator across 4 lanes (xor 1, then 2)
__device__ __forceinline__ void comb4(u64 &acc) {
    u64 o = __shfl_xor_sync(0xffffffffu, acc, 1);
    float a0, a1, b0, b1;
    upk2(acc, a0, a1); upk2(o, b0, b1);
    acc = pk2(a0 + b0, a1 + b1);
    o = __shfl_xor_sync(0xffffffffu, acc, 2);
    upk2(acc, a0, a1); upk2(o, b0, b1);
    acc = pk2(a0 + b0, a1 + b1);
}

#define LDSM4(r0, r1, r2, r3, addr) \
    asm volatile("ldmatrix.sync.aligned.m8n8.x4.shared.b16 {%0,%1,%2,%3}, [%4];" \
        : "=r"(r0), "=r"(r1), "=r"(r2), "=r"(r3) : "r"(addr))

#define MMA16816(d, a0, a1, a2, a3, b0, b1) \
    asm volatile("mma.sync.aligned.m16n8k16.row.col.f32.bf16.bf16.f32 " \
        "{%0,%1,%2,%3}, {%4,%5,%6,%7}, {%8,%9}, {%0,%1,%2,%3};" \
        : "+f"((d)[0]), "+f"((d)[1]), "+f"((d)[2]), "+f"((d)[3]) \
        : "r"(a0), "r"(a1), "r"(a2), "r"(a3), "r"(b0), "r"(b1))

#define BAR_HALF(id) \
    asm volatile("bar.sync %0, 256;" :: "r"(id) : "memory")

// shared prep routine: one element of the split/swizzled weight tables
__device__ __forceinline__ void prep_one(int idx, const float* __restrict__ Wih,
                                         const float* __restrict__ Whh)
{
    int n = idx >> 7;
    int k = idx & 127;
    int gate = n & 3, q = n >> 2;
    int r  = gate * 64 + q;
    int ks = k & 63;
    float wih = Wih[r * 64 + ks];
    float wc  = wih + Whh[r * 64 + ks];
    bool lo = (k >= 64);
    __nv_bfloat16 vih, vc;
    {
        __nv_bfloat16 hi = __float2bfloat16_rn(wih);
        vih = lo ? __float2bfloat16_rn(wih - __bfloat162float(hi)) : hi;
    }
    {
        __nv_bfloat16 hi = __float2bfloat16_rn(wc);
        vc = lo ? __float2bfloat16_rn(wc - __bfloat162float(hi)) : hi;
    }
    int off = n * 256 + k * 2;
    off ^= (n & 7) << 4;
    *(__nv_bfloat16*)(g_Wih_sw + off) = vih;
    *(__nv_bfloat16*)(g_Wc_sw  + off) = vc;
}

__device__ __forceinline__ void bn_finalize_partial(const float* __restrict__ part,
                                                    float* s_red, int tid)
{
    if (tid < 128) {
        int f = tid & 31, p = tid >> 5;
        float s = 0.f, q = 0.f;
        const float* base = part + p * 32 * 64;
#pragma unroll 8
        for (int b = 0; b < 32; b++) { s += base[b * 64 + f]; q += base[b * 64 + 32 + f]; }
        s_red[p * 64 + f] = s;
        s_red[p * 64 + 32 + f] = q;
    }
}
__device__ __forceinline__ void bn_finalize_combine(const float* s_red,
                                                    const float* __restrict__ gamma,
                                                    const float* __restrict__ beta,
                                                    float* s_bn, int tid)
{
    if (tid < 32) {
        int f = tid;
        float s = 0.f, q = 0.f;
#pragma unroll
        for (int p = 0; p < 4; p++) { s += s_red[p * 64 + f]; q += s_red[p * 64 + 32 + f]; }
        float mean = s * (1.f / (float)BATCH);
        float var  = q * (1.f / (float)BATCH) - mean * mean;
        float sc   = gamma[f] * rsqrtf(var + 1e-5f);
        s_bn[f] = sc; s_bn[32 + f] = beta[f] - mean * sc;
    }
}

// =====================================================================
// K1: A1 = concat(x0,x1,x2) @ W1^T + b1 ; partial stats ; weight-prep tail
// grid 128, block 512 (4 threads per row, k split 4-way), smem 53440 B
// W1 smem layout: quarter blocks of 769 ull2 (12304 B) -> bank offset 4/quarter
// =====================================================================
__global__ void k_mlp1(const float* __restrict__ x0, const float* __restrict__ x1,
                       const float* __restrict__ x2, const float* __restrict__ W1,
                       const float* __restrict__ b1,
                       const float* __restrict__ Wih, const float* __restrict__ Whh)
{
    extern __shared__ float sm[];
    float* s_w   = sm;            // 12304 floats (4 x 3076)
    float* s_b   = sm + 12304;    // 32
    float* s_red = sm + 12336;    // 16 warps * 64
    int tid = threadIdx.x;
    for (int i = tid; i < 12288; i += 512) {
        int h = i / 384, k = i - h * 384;
        int c = k >> 2, qq = c & 3, j = c >> 2;
        s_w[qq * 3076 + j * 128 + (k & 3) * 32 + h] = W1[i];
    }
    if (tid < 32) s_b[tid] = b1[tid];
    {
        int gid = blockIdx.x * 512 + tid;
        if (gid < 32768) prep_one(gid, Wih, Whh);
    }
    __syncthreads();

    int q4  = tid & 3;
    int row = blockIdx.x * 128 + (tid >> 2);

    u64 acc[16];
#pragma unroll
    for (int i = 0; i < 16; i++) acc[i] = 0ull;
    const float4* px0 = (const float4*)(x0 + (size_t)row * NOUT);
    const float4* px1 = (const float4*)(x1 + (size_t)row * NOUT) - 32;
    const float4* px2 = (const float4*)(x2 + (size_t)row * NOUT) - 64;
    const ulonglong2* wb = (const ulonglong2*)s_w + q4 * 769;

#pragma unroll 4
    for (int j = 0; j < 24; j++) {
        const float4* bp = (j < 8) ? px0 : (j < 16) ? px1 : px2;
        int i = 4 * j + q4;
        float4 xv = bp[i];
        const ulonglong2* wr = wb + j * 32;
#pragma unroll
        for (int c = 0; c < 4; c++) {
            float xc = (c == 0) ? xv.x : (c == 1) ? xv.y : (c == 2) ? xv.z : xv.w;
            u64 xp2 = pk2(xc, xc);
#pragma unroll
            for (int f = 0; f < 8; f++) {
                ulonglong2 wv = wr[c * 8 + f];
                ffma2(acc[2 * f], xp2, wv.x);
                ffma2(acc[2 * f + 1], xp2, wv.y);
            }
        }
    }
#pragma unroll
    for (int f = 0; f < 16; f++) comb4(acc[f]);

    float a[32];
#pragma unroll
    for (int f = 0; f < 16; f++) upk2(acc[f], a[2 * f], a[2 * f + 1]);
#pragma unroll
    for (int f = 0; f < 32; f++) a[f] += s_b[f];

    if (q4 == 0) {
        float4* outp = (float4*)(g_A1 + (size_t)row * 32);
#pragma unroll
        for (int i = 0; i < 8; i++)
            outp[i] = make_float4(a[4 * i], a[4 * i + 1], a[4 * i + 2], a[4 * i + 3]);
    }

    int lane = tid & 31, warp = tid >> 5;
#pragma unroll
    for (int f = 0; f < 32; f++) {
        float sv = (q4 == 0) ? a[f] : 0.f;
        float qv = sv * a[f];
#pragma unroll
        for (int off = 16; off >= 1; off >>= 1) {
            sv += __shfl_xor_sync(0xffffffffu, sv, off);
            qv += __shfl_xor_sync(0xffffffffu, qv, off);
        }
        if (lane == 0) { s_red[warp * 64 + f] = sv; s_red[warp * 64 + 32 + f] = qv; }
    }
    __syncthreads();
    if (tid < 64) {
        float t = 0.f;
#pragma unroll
        for (int w = 0; w < 16; w++) t += s_red[w * 64 + tid];
        g_part1[blockIdx.x * 64 + tid] = t;
    }
}

// =====================================================================
// K2: bn1 finalize (redundant); h1 = relu(bn1(A1)); A2 = h1 @ W2^T + b2
// grid 128, block 512 (4 threads/row). W2 quarter blocks 65 ull2 each.
// =====================================================================
__global__ void k_mlp2(const float* __restrict__ W2, const float* __restrict__ b2,
                       const float* __restrict__ g1, const float* __restrict__ beta1)
{
    __shared__ float s_w[1040];    // 4 x 260 floats (65 ull2)
    __shared__ float s_bn[64];
    __shared__ float s_b[32];
    __shared__ float s_red[1024];
    int tid = threadIdx.x;
    for (int i = tid; i < 1024; i += 512) {
        int h = i >> 5, k = i & 31;
        int qq = k >> 3, kl = k & 7;
        s_w[qq * 260 + kl * 32 + h] = W2[i];
    }
    if (tid < 32) s_b[tid] = b2[tid];
    bn_finalize_partial(g_part1, s_red, tid);
    __syncthreads();
    bn_finalize_combine(s_red, g1, beta1, s_bn, tid);
    __syncthreads();

    int q4  = tid & 3;
    int row = blockIdx.x * 128 + (tid >> 2);
    int kb  = q4 * 8;

    float hv[8];
    const float4* ip = (const float4*)(g_A1 + (size_t)row * 32);
#pragma unroll
    for (int i = 0; i < 2; i++) {
        float4 v = ip[2 * q4 + i];
        int k0 = kb + 4 * i;
        hv[4 * i]     = fmaxf(fmaf(v.x, s_bn[k0],     s_bn[32 + k0]),     0.f);
        hv[4 * i + 1] = fmaxf(fmaf(v.y, s_bn[k0 + 1], s_bn[32 + k0 + 1]), 0.f);
        hv[4 * i + 2] = fmaxf(fmaf(v.z, s_bn[k0 + 2], s_bn[32 + k0 + 2]), 0.f);
        hv[4 * i + 3] = fmaxf(fmaf(v.w, s_bn[k0 + 3], s_bn[32 + k0 + 3]), 0.f);
    }
    u64 acc[16];
#pragma unroll
    for (int i = 0; i < 16; i++) acc[i] = 0ull;
    const ulonglong2* wb = (const ulonglong2*)s_w + q4 * 65;
#pragma unroll
    for (int k = 0; k < 8; k++) {
        u64 xp2 = pk2(hv[k], hv[k]);
        const ulonglong2* wr = wb + k * 8;
#pragma unroll
        for (int f = 0; f < 8; f++) {
            ulonglong2 wv = wr[f];
            ffma2(acc[2 * f], xp2, wv.x);
            ffma2(acc[2 * f + 1], xp2, wv.y);
        }
    }
#pragma unroll
    for (int f = 0; f < 16; f++) comb4(acc[f]);

    float a[32];
#pragma unroll
    for (int f = 0; f < 16; f++) upk2(acc[f], a[2 * f], a[2 * f + 1]);
#pragma unroll
    for (int f = 0; f < 32; f++) a[f] += s_b[f];

    if (q4 == 0) {
        float4* outp = (float4*)(g_A2 + (size_t)row * 32);
#pragma unroll
        for (int i = 0; i < 8; i++)
            outp[i] = make_float4(a[4 * i], a[4 * i + 1], a[4 * i + 2], a[4 * i + 3]);
    }

    int lane = tid & 31, warp = tid >> 5;
#pragma unroll
    for (int f = 0; f < 32; f++) {
        float sv = (q4 == 0) ? a[f] : 0.f;
        float qv = sv * a[f];
#pragma unroll
        for (int off = 16; off >= 1; off >>= 1) {
            sv += __shfl_xor_sync(0xffffffffu, sv, off);
            qv += __shfl_xor_sync(0xffffffffu, qv, off);
        }
        if (lane == 0) { s_red[warp * 64 + f] = sv; s_red[warp * 64 + 32 + f] = qv; }
    }
    __syncthreads();
    if (tid < 64) {
        float t = 0.f;
#pragma unroll
        for (int w = 0; w < 16; w++) t += s_red[w * 64 + tid];
        g_part2[blockIdx.x * 64 + tid] = t;
    }
}

// =====================================================================
// K3: bn2 finalize (redundant); h2 = relu(bn2(A2)); m = h2 @ W3^T + b3
// grid 128, block 512 (4 threads/row). W3 quarter blocks 129 ull2 each.
// =====================================================================
__global__ void k_mlp3(const float* __restrict__ W3, const float* __restrict__ b3,
                       const float* __restrict__ g2, const float* __restrict__ beta2)
{
    __shared__ float s_w[2064];    // 4 x 516 floats (129 ull2)
    __shared__ float s_bn[64];
    __shared__ float s_b[64];
    __shared__ float s_red[1024];
    int tid = threadIdx.x;
    for (int i = tid; i < 2048; i += 512) {
        int j = i >> 5, k = i & 31;
        int qq = k >> 3, kl = k & 7;
        s_w[qq * 516 + kl * 64 + j] = W3[i];
    }
    if (tid < 64) s_b[tid] = b3[tid];
    bn_finalize_partial(g_part2, s_red, tid);
    __syncthreads();
    bn_finalize_combine(s_red, g2, beta2, s_bn, tid);
    __syncthreads();

    int q4  = tid & 3;
    int row = blockIdx.x * 128 + (tid >> 2);
    int kb  = q4 * 8;

    float hv[8];
    const float4* ip = (const float4*)(g_A2 + (size_t)row * 32);
#pragma unroll
    for (int i = 0; i < 2; i++) {
        float4 v = ip[2 * q4 + i];
        int k0 = kb + 4 * i;
        hv[4 * i]     = fmaxf(fmaf(v.x, s_bn[k0],     s_bn[32 + k0]),     0.f);
        hv[4 * i + 1] = fmaxf(fmaf(v.y, s_bn[k0 + 1], s_bn[32 + k0 + 1]), 0.f);
        hv[4 * i + 2] = fmaxf(fmaf(v.z, s_bn[k0 + 2], s_bn[32 + k0 + 2]), 0.f);
        hv[4 * i + 3] = fmaxf(fmaf(v.w, s_bn[k0 + 3], s_bn[32 + k0 + 3]), 0.f);
    }
    u64 acc[32];
#pragma unroll
    for (int i = 0; i < 32; i++) acc[i] = 0ull;
    const ulonglong2* wb = (const ulonglong2*)s_w + q4 * 129;
#pragma unroll
    for (int k = 0; k < 8; k++) {
        u64 xp2 = pk2(hv[k], hv[k]);
        const ulonglong2* wr = wb + k * 16;
#pragma unroll
        for (int f = 0; f < 16; f++) {
            ulonglong2 wv = wr[f];
            ffma2(acc[2 * f], xp2, wv.x);
            ffma2(acc[2 * f + 1], xp2, wv.y);
        }
    }
#pragma unroll
    for (int f = 0; f < 32; f++) comb4(acc[f]);

    if (q4 == 0) {
        float4* outp = (float4*)(g_m + (size_t)row * 64);
#pragma unroll
        for (int i = 0; i < 16; i++) {
            float a, b, c, d;
            upk2(acc[2 * i], a, b);
            upk2(acc[2 * i + 1], c, d);
            outp[i] = make_float4(a + s_b[4 * i], b + s_b[4 * i + 1],
                                  c + s_b[4 * i + 2], d + s_b[4 * i + 3]);
        }
    }
}

// =====================================================================
// LSTM via mma.sync bf16 (unchanged from R11 pass).
// =====================================================================
#define SW_OFF  0
#define SA0_OFF 65536
#define SC_OFF  131072
#define SBC_OFF 172032
#define SMEM_LSTM 173056

__device__ __forceinline__ void init_A(u8* smem, const float* __restrict__ gm,
                                       int s0, int tid)
{
    int row = tid >> 2, qtr = tid & 3;
    const float* src = gm + (size_t)(s0 + row) * 64 + qtr * 16;
    float v[16];
#pragma unroll
    for (int j = 0; j < 4; j++) {
        float4 t4 = *(const float4*)(src + 4 * j);
        v[4 * j] = t4.x; v[4 * j + 1] = t4.y; v[4 * j + 2] = t4.z; v[4 * j + 3] = t4.w;
    }
    int rowbase = SA0_OFF + row * 256;
    int kb = qtr * 32;
    int swz = (row & 7) << 4;
#pragma unroll
    for (int c4 = 0; c4 < 2; c4++) {
        uint4 hi4, lo4;
        u32* hp = (u32*)&hi4; u32* lp = (u32*)&lo4;
#pragma unroll
        for (int e = 0; e < 4; e++) {
            float a = v[c4 * 8 + 2 * e], b = v[c4 * 8 + 2 * e + 1];
            __nv_bfloat162 th = __floats2bfloat162_rn(a, b);
            float la = a - __bfloat162float(th.x);
            float lb = b - __bfloat162float(th.y);
            __nv_bfloat162 tl = __floats2bfloat162_rn(la, lb);
            hp[e] = *(u32*)&th;
            lp[e] = *(u32*)&tl;
        }
        int offh = rowbase + ((kb + c4 * 16) ^ swz);
        *(uint4*)(smem + offh)       = hi4;
        *(uint4*)(smem + offh + 128) = lo4;
    }
}

__global__ __launch_bounds__(512, 1)
void k_lstm_mma(const float* __restrict__ bih, const float* __restrict__ bhh,
                float* __restrict__ out)
{
    extern __shared__ u8 smem[];
    float* sCf  = (float*)(smem + SC_OFF);
    float* sBCf = (float*)(smem + SBC_OFF);

    int tid  = threadIdx.x;
    int wid  = tid >> 5;
    int lane = tid & 31;
    int s0   = blockIdx.x * 128;

    {
        uint4* d = (uint4*)(smem + SW_OFF);
        const uint4* s = (const uint4*)g_Wih_sw;
        for (int i = tid; i < 4096; i += 512) d[i] = s[i];
    }
    if (tid < 256) {
        int n = tid, r = (n & 3) * 64 + (n >> 2);
        sBCf[n] = bih[r] + bhh[r];
    }
    for (int i = tid; i < 512 * 20; i += 512) sCf[i] = 0.f;
    init_A(smem, g_m, s0, tid);
    __syncthreads();

    int warp_m = wid & 1;
    int warp_n = wid >> 1;
    int lane8 = lane & 7;
    u32 sbase = smem_u32(smem);

    int rA = warp_m * 64 + lane8 + (lane & 8);
    int kA8b = (lane & 16) ? 16 : 0;
    int swzA = (rA & 7) << 4;
    u32 aRow = sbase + SA0_OFF + (u32)(rA * 256);

    int rB = warp_n * 32 + lane8 + ((lane & 16) >> 1);
    int kB8b = (lane & 8) ? 16 : 0;
    int swzB = (rB & 7) << 4;
    u32 bRow = sbase + SW_OFF + (u32)(rB * 256);

    int g    = lane >> 2;
    int oddl = lane & 1;
    int b    = (lane & 3) >> 1;
    int cbase = tid * 20;
    int barid = 1 + warp_m;

    float b0v[4], b1v[4];
#pragma unroll
    for (int nt = 0; nt < 4; nt++) {
        int nc = warp_n * 32 + nt * 8 + 2 * (lane & 3);
        b0v[nt] = sBCf[nc];
        b1v[nt] = sBCf[nc + 1];
    }

    int rowE0 = warp_m * 64 + g + 8 * oddl;
    u32 colOff = (u32)((16 * warp_n + 8 * b) ^ (g << 4));

#pragma unroll 1
    for (int t = 0; t < 26; t++) {
        u32 aBuf = aRow + ((t & 1) << 15);

        float acc[4][4][4];
#pragma unroll
        for (int mt = 0; mt < 4; mt++)
#pragma unroll
            for (int nt = 0; nt < 4; nt++)
#pragma unroll
                for (int e = 0; e < 4; e++) acc[mt][nt][e] = 0.f;

#pragma unroll
        for (int c = 0; c < 4; c++) {
            u32 af[4][4], bf[2][4];
            u32 aoff = (u32)((kA8b + 32 * c) ^ swzA);
#pragma unroll
            for (int mt = 0; mt < 4; mt++)
                LDSM4(af[mt][0], af[mt][1], af[mt][2], af[mt][3],
                      aBuf + mt * 4096 + aoff);
            u32 boffh = (u32)((kB8b + 32 * c) ^ swzB);
#pragma unroll
            for (int np = 0; np < 2; np++)
                LDSM4(bf[np][0], bf[np][1], bf[np][2], bf[np][3],
                      bRow + np * 4096 + boffh);
#pragma unroll
            for (int mt = 0; mt < 4; mt++)
#pragma unroll
                for (int np = 0; np < 2; np++) {
                    MMA16816(acc[mt][2 * np],     af[mt][0], af[mt][1], af[mt][2], af[mt][3],
                             bf[np][0], bf[np][1]);
                    MMA16816(acc[mt][2 * np + 1], af[mt][0], af[mt][1], af[mt][2], af[mt][3],
                             bf[np][2], bf[np][3]);
                }
            u32 boffl = (u32)((kB8b + 32 * (c + 4)) ^ swzB);
#pragma unroll
            for (int np = 0; np < 2; np++)
                LDSM4(bf[np][0], bf[np][1], bf[np][2], bf[np][3],
                      bRow + np * 4096 + boffl);
#pragma unroll
            for (int mt = 0; mt < 4; mt++)
#pragma unroll
                for (int np = 0; np < 2; np++) {
                    MMA16816(acc[mt][2 * np],     af[mt][0], af[mt][1], af[mt][2], af[mt][3],
                             bf[np][0], bf[np][1]);
                    MMA16816(acc[mt][2 * np + 1], af[mt][0], af[mt][1], af[mt][2], af[mt][3],
                             bf[np][2], bf[np][3]);
                }
        }
#pragma unroll
        for (int c = 0; c < 4; c++) {
            u32 af[4][4], bf[2][4];
            u32 aoff = (u32)((kA8b + 32 * (c + 4)) ^ swzA);
#pragma unroll
            for (int mt = 0; mt < 4; mt++)
                LDSM4(af[mt][0], af[mt][1], af[mt][2], af[mt][3],
                      aBuf + mt * 4096 + aoff);
            u32 boffh = (u32)((kB8b + 32 * c) ^ swzB);
#pragma unroll
            for (int np = 0; np < 2; np++)
                LDSM4(bf[np][0], bf[np][1], bf[np][2], bf[np][3],
                      bRow + np * 4096 + boffh);
#pragma unroll
            for (int mt = 0; mt < 4; mt++)
#pragma unroll
                for (int np = 0; np < 2; np++) {
                    MMA16816(acc[mt][2 * np],     af[mt][0], af[mt][1], af[mt][2], af[mt][3],
                             bf[np][0], bf[np][1]);
                    MMA16816(acc[mt][2 * np + 1], af[mt][0], af[mt][1], af[mt][2], af[mt][3],
                             bf[np][2], bf[np][3]);
                }
        }

        u32 wBase = (u32)(SA0_OFF + (((t & 1) ^ 1) << 15) + rowE0 * 256) + colOff;
#pragma unroll
        for (int mt = 0; mt < 4; mt++) {
            int row = rowE0 + mt * 16;
            float4 cva = *(float4*)&sCf[cbase + mt * 4];
            float cc[4] = {cva.x, cva.y, cva.z, cva.w};
            float hvv[4];
#pragma unroll
            for (int nt = 0; nt < 4; nt++) {
                float v0 = acc[mt][nt][0] + b0v[nt];
                float v1 = acc[mt][nt][1] + b1v[nt];
                float v2 = acc[mt][nt][2] + b0v[nt];
                float v3 = acc[mt][nt][3] + b1v[nt];
                float o0 = __shfl_xor_sync(0xffffffffu, v0, 1);
                float o1 = __shfl_xor_sync(0xffffffffu, v1, 1);
                float o2 = __shfl_xor_sync(0xffffffffu, v2, 1);
                float o3 = __shfl_xor_sync(0xffffffffu, v3, 1);
                float gi = oddl ? o2 : v0;
                float gf = oddl ? o3 : v1;
                float gg = oddl ? v2 : o0;
                float go = oddl ? v3 : o1;
                float si = fmaf(tanhfast(0.5f * gi), 0.5f, 0.5f);
                float sf = fmaf(tanhfast(0.5f * gf), 0.5f, 0.5f);
                float so = fmaf(tanhfast(0.5f * go), 0.5f, 0.5f);
                float tg = tanhfast(gg);
                float cn = fmaf(sf, cc[nt], si * tg);
                cc[nt] = cn;
                hvv[nt] = so * tanhfast(cn);
            }
            *(float4*)&sCf[cbase + mt * 4] = make_float4(cc[0], cc[1], cc[2], cc[3]);

            float p0 = __shfl_xor_sync(0xffffffffu, hvv[0], 2);
            float p1 = __shfl_xor_sync(0xffffffffu, hvv[1], 2);
            float p2 = __shfl_xor_sync(0xffffffffu, hvv[2], 2);
            float p3 = __shfl_xor_sync(0xffffffffu, hvv[3], 2);
            float w0 = b ? p2     : hvv[0];
            float w1 = b ? hvv[2] : p0;
            float w2 = b ? p3     : hvv[1];
            float w3 = b ? hvv[3] : p1;

            __nv_bfloat162 H01 = __floats2bfloat162_rn(w0, w1);
            __nv_bfloat162 H23 = __floats2bfloat162_rn(w2, w3);
            float l0 = w0 - __bfloat162float(H01.x);
            float l1 = w1 - __bfloat162float(H01.y);
            float l2 = w2 - __bfloat162float(H23.x);
            float l3 = w3 - __bfloat162float(H23.y);
            __nv_bfloat162 L01 = __floats2bfloat162_rn(l0, l1);
            __nv_bfloat162 L23 = __floats2bfloat162_rn(l2, l3);

            u32 addr = wBase + (u32)(mt * 4096);
            uint2 hv2 = make_uint2(*(u32*)&H01, *(u32*)&H23);
            uint2 lv2 = make_uint2(*(u32*)&L01, *(u32*)&L23);
            *(uint2*)(smem + addr)       = hv2;
            *(uint2*)(smem + addr + 128) = lv2;

            if (t >= 1) {
                float4* op = (float4*)(out + ((size_t)(s0 + row) * NPRED + (t - 1)) * 64
                                       + 8 * warp_n + 4 * b);
                *op = make_float4(w0, w1, w2, w3);
            }
        }

        if (t == 0) {
            __syncthreads();
            uint4* d = (uint4*)(smem + SW_OFF);
            const uint4* src = (const uint4*)g_Wc_sw;
            for (int i = tid; i < 4096; i += 512) d[i] = src[i];
            __syncthreads();
        } else {
            BAR_HALF(barid);
        }
    }
}

// =====================================================================
extern "C" void kernel_launch(void* const* d_in, const int* in_sizes, int n_in,
                              void* d_out, int out_size)
{
    const float* x0    = (const float*)d_in[0];
    const float* x1    = (const float*)d_in[1];
    const float* x2    = (const float*)d_in[2];
    const float* W1    = (const float*)d_in[3];
    const float* b1    = (const float*)d_in[4];
    const float* g1    = (const float*)d_in[5];
    const float* beta1 = (const float*)d_in[6];
    const float* W2    = (const float*)d_in[7];
    const float* b2    = (const float*)d_in[8];
    const float* g2    = (const float*)d_in[9];
    const float* beta2 = (const float*)d_in[10];
    const float* W3    = (const float*)d_in[11];
    const float* b3    = (const float*)d_in[12];
    const float* Wih   = (const float*)d_in[13];
    const float* Whh   = (const float*)d_in[14];
    const float* bih   = (const float*)d_in[15];
    const float* bhh   = (const float*)d_in[16];
    float* out = (float*)d_out;

    cudaFuncSetAttribute(k_mlp1, cudaFuncAttributeMaxDynamicSharedMemorySize, 53440);
    cudaFuncSetAttribute(k_lstm_mma, cudaFuncAttributeMaxDynamicSharedMemorySize, SMEM_LSTM);

    k_mlp1<<<128, 512, 53440>>>(x0, x1, x2, W1, b1, Wih, Whh);
    k_mlp2<<<128, 512>>>(W2, b2, g1, beta1);
    k_mlp3<<<128, 512>>>(W3, b3, g2, beta2);
    k_lstm_mma<<<128, 512, SMEM_LSTM>>>(bih, bhh, out);
}

// round 15
// speedup vs baseline: 1.0985x; 1.0985x over previous
#include <cuda_runtime.h>
#include <cuda_bf16.h>

typedef unsigned int u32;
typedef unsigned long long u64;
typedef unsigned char u8;

#define BATCH 16384
#define NOUT  128
#define LH    64
#define NPRED 25

// ---------------- scratch ----------------
__device__ float g_A1[BATCH * 32];
__device__ float g_A2[BATCH * 32];
__device__ float g_m [BATCH * LH];
__device__ float g_part1[128 * 64];
__device__ float g_part2[128 * 64];
// bf16-split weights, col interleave n = 32*(q>>3) + 8*gate + (q&7):
// 256 n-rows x 128 k (k 0-63 W_hi, 64-127 W_lo), row 256B, swizzle ^=(n&7)<<4
__device__ u8 g_Wih_sw[65536];
__device__ u8 g_Wc_sw [65536];

// ---------------- helpers ----------------
__device__ __forceinline__ u64 pk2(float a, float b) {
    u64 r; asm("mov.b64 %0,{%1,%2};" : "=l"(r) : "f"(a), "f"(b)); return r;
}
__device__ __forceinline__ void upk2(u64 v, float &a, float &b) {
    asm("mov.b64 {%0,%1},%2;" : "=f"(a), "=f"(b) : "l"(v));
}
__device__ __forceinline__ void ffma2(u64 &d, u64 a, u64 b) {
    asm("fma.rn.f32x2 %0,%1,%2,%0;" : "+l"(d) : "l"(a), "l"(b));
}
__device__ __forceinline__ float tanhfast(float x) {
    float r; asm("tanh.approx.f32 %0,%1;" : "=f"(r) : "f"(x)); return r;
}
__device__ __forceinline__ u32 smem_u32(const void* p) {
    u32 a; asm("{ .reg .u64 t; cvta.to.shared.u64 t, %1; cvt.u32.u64 %0, t; }"
               : "=r"(a) : "l"(p));
    return a;
}
__device__ __forceinline__ void comb4(u64 &acc) {
    u64 o = __shfl_xor_sync(0xffffffffu, acc, 1);
    float a0, a1, b0, b1;
    upk2(acc, a0, a1); upk2(o, b0, b1);
    acc = pk2(a0 + b0, a1 + b1);
    o = __shfl_xor_sync(0xffffffffu, acc, 2);
    upk2(acc, a0, a1); upk2(o, b0, b1);
    acc = pk2(a0 + b0, a1 + b1);
}

#define LDSM4(r0, r1, r2, r3, addr) \
    asm volatile("ldmatrix.sync.aligned.m8n8.x4.shared.b16 {%0,%1,%2,%3}, [%4];" \
        : "=r"(r0), "=r"(r1), "=r"(r2), "=r"(r3) : "r"(addr))

#define MMA16816(d, a0, a1, a2, a3, b0, b1) \
    asm volatile("mma.sync.aligned.m16n8k16.row.col.f32.bf16.bf16.f32 " \
        "{%0,%1,%2,%3}, {%4,%5,%6,%7}, {%8,%9}, {%0,%1,%2,%3};" \
        : "+f"((d)[0]), "+f"((d)[1]), "+f"((d)[2]), "+f"((d)[3]) \
        : "r"(a0), "r"(a1), "r"(a2), "r"(a3), "r"(b0), "r"(b1))

#define BAR_HALF(id) \
    asm volatile("bar.sync %0, 256;" :: "r"(id) : "memory")

// n-col -> original weight row mapping (shuffle-free epilogue layout)
__device__ __forceinline__ int n_to_row(int n) {
    int gate = (n >> 3) & 3;
    int q = ((n >> 5) << 3) + (n & 7);
    return gate * 64 + q;
}

// shared prep routine: one element of the split/swizzled weight tables
__device__ __forceinline__ void prep_one(int idx, const float* __restrict__ Wih,
                                         const float* __restrict__ Whh)
{
    int n = idx >> 7;
    int k = idx & 127;
    int r = n_to_row(n);
    int ks = k & 63;
    float wih = Wih[r * 64 + ks];
    float wc  = wih + Whh[r * 64 + ks];
    bool lo = (k >= 64);
    __nv_bfloat16 vih, vc;
    {
        __nv_bfloat16 hi = __float2bfloat16_rn(wih);
        vih = lo ? __float2bfloat16_rn(wih - __bfloat162float(hi)) : hi;
    }
    {
        __nv_bfloat16 hi = __float2bfloat16_rn(wc);
        vc = lo ? __float2bfloat16_rn(wc - __bfloat162float(hi)) : hi;
    }
    int off = n * 256 + k * 2;
    off ^= (n & 7) << 4;
    *(__nv_bfloat16*)(g_Wih_sw + off) = vih;
    *(__nv_bfloat16*)(g_Wc_sw  + off) = vc;
}

__device__ __forceinline__ void bn_finalize_partial(const float* __restrict__ part,
                                                    float* s_red, int tid)
{
    if (tid < 128) {
        int f = tid & 31, p = tid >> 5;
        float s = 0.f, q = 0.f;
        const float* base = part + p * 32 * 64;
#pragma unroll 8
        for (int b = 0; b < 32; b++) { s += base[b * 64 + f]; q += base[b * 64 + 32 + f]; }
        s_red[p * 64 + f] = s;
        s_red[p * 64 + 32 + f] = q;
    }
}
__device__ __forceinline__ void bn_finalize_combine(const float* s_red,
                                                    const float* __restrict__ gamma,
                                                    const float* __restrict__ beta,
                                                    float* s_bn, int tid)
{
    if (tid < 32) {
        int f = tid;
        float s = 0.f, q = 0.f;
#pragma unroll
        for (int p = 0; p < 4; p++) { s += s_red[p * 64 + f]; q += s_red[p * 64 + 32 + f]; }
        float mean = s * (1.f / (float)BATCH);
        float var  = q * (1.f / (float)BATCH) - mean * mean;
        float sc   = gamma[f] * rsqrtf(var + 1e-5f);
        s_bn[f] = sc; s_bn[32 + f] = beta[f] - mean * sc;
    }
}

// =====================================================================
// K1 (unchanged from R14 pass)
// =====================================================================
__global__ void k_mlp1(const float* __restrict__ x0, const float* __restrict__ x1,
                       const float* __restrict__ x2, const float* __restrict__ W1,
                       const float* __restrict__ b1,
                       const float* __restrict__ Wih, const float* __restrict__ Whh)
{
    extern __shared__ float sm[];
    float* s_w   = sm;
    float* s_b   = sm + 12304;
    float* s_red = sm + 12336;
    int tid = threadIdx.x;
    for (int i = tid; i < 12288; i += 512) {
        int h = i / 384, k = i - h * 384;
        int c = k >> 2, qq = c & 3, j = c >> 2;
        s_w[qq * 3076 + j * 128 + (k & 3) * 32 + h] = W1[i];
    }
    if (tid < 32) s_b[tid] = b1[tid];
    {
        int gid = blockIdx.x * 512 + tid;
        if (gid < 32768) prep_one(gid, Wih, Whh);
    }
    __syncthreads();

    int q4  = tid & 3;
    int row = blockIdx.x * 128 + (tid >> 2);

    u64 acc[16];
#pragma unroll
    for (int i = 0; i < 16; i++) acc[i] = 0ull;
    const float4* px0 = (const float4*)(x0 + (size_t)row * NOUT);
    const float4* px1 = (const float4*)(x1 + (size_t)row * NOUT) - 32;
    const float4* px2 = (const float4*)(x2 + (size_t)row * NOUT) - 64;
    const ulonglong2* wb = (const ulonglong2*)s_w + q4 * 769;

#pragma unroll 4
    for (int j = 0; j < 24; j++) {
        const float4* bp = (j < 8) ? px0 : (j < 16) ? px1 : px2;
        int i = 4 * j + q4;
        float4 xv = bp[i];
        const ulonglong2* wr = wb + j * 32;
#pragma unroll
        for (int c = 0; c < 4; c++) {
            float xc = (c == 0) ? xv.x : (c == 1) ? xv.y : (c == 2) ? xv.z : xv.w;
            u64 xp2 = pk2(xc, xc);
#pragma unroll
            for (int f = 0; f < 8; f++) {
                ulonglong2 wv = wr[c * 8 + f];
                ffma2(acc[2 * f], xp2, wv.x);
                ffma2(acc[2 * f + 1], xp2, wv.y);
            }
        }
    }
#pragma unroll
    for (int f = 0; f < 16; f++) comb4(acc[f]);

    float a[32];
#pragma unroll
    for (int f = 0; f < 16; f++) upk2(acc[f], a[2 * f], a[2 * f + 1]);
#pragma unroll
    for (int f = 0; f < 32; f++) a[f] += s_b[f];

    if (q4 == 0) {
        float4* outp = (float4*)(g_A1 + (size_t)row * 32);
#pragma unroll
        for (int i = 0; i < 8; i++)
            outp[i] = make_float4(a[4 * i], a[4 * i + 1], a[4 * i + 2], a[4 * i + 3]);
    }

    int lane = tid & 31, warp = tid >> 5;
#pragma unroll
    for (int f = 0; f < 32; f++) {
        float sv = (q4 == 0) ? a[f] : 0.f;
        float qv = sv * a[f];
#pragma unroll
        for (int off = 16; off >= 1; off >>= 1) {
            sv += __shfl_xor_sync(0xffffffffu, sv, off);
            qv += __shfl_xor_sync(0xffffffffu, qv, off);
        }
        if (lane == 0) { s_red[warp * 64 + f] = sv; s_red[warp * 64 + 32 + f] = qv; }
    }
    __syncthreads();
    if (tid < 64) {
        float t = 0.f;
#pragma unroll
        for (int w = 0; w < 16; w++) t += s_red[w * 64 + tid];
        g_part1[blockIdx.x * 64 + tid] = t;
    }
}

// =====================================================================
// K2 (unchanged from R14 pass)
// =====================================================================
__global__ void k_mlp2(const float* __restrict__ W2, const float* __restrict__ b2,
                       const float* __restrict__ g1, const float* __restrict__ beta1)
{
    __shared__ float s_w[1040];
    __shared__ float s_bn[64];
    __shared__ float s_b[32];
    __shared__ float s_red[1024];
    int tid = threadIdx.x;
    for (int i = tid; i < 1024; i += 512) {
        int h = i >> 5, k = i & 31;
        int qq = k >> 3, kl = k & 7;
        s_w[qq * 260 + kl * 32 + h] = W2[i];
    }
    if (tid < 32) s_b[tid] = b2[tid];
    bn_finalize_partial(g_part1, s_red, tid);
    __syncthreads();
    bn_finalize_combine(s_red, g1, beta1, s_bn, tid);
    __syncthreads();

    int q4  = tid & 3;
    int row = blockIdx.x * 128 + (tid >> 2);
    int kb  = q4 * 8;

    float hv[8];
    const float4* ip = (const float4*)(g_A1 + (size_t)row * 32);
#pragma unroll
    for (int i = 0; i < 2; i++) {
        float4 v = ip[2 * q4 + i];
        int k0 = kb + 4 * i;
        hv[4 * i]     = fmaxf(fmaf(v.x, s_bn[k0],     s_bn[32 + k0]),     0.f);
        hv[4 * i + 1] = fmaxf(fmaf(v.y, s_bn[k0 + 1], s_bn[32 + k0 + 1]), 0.f);
        hv[4 * i + 2] = fmaxf(fmaf(v.z, s_bn[k0 + 2], s_bn[32 + k0 + 2]), 0.f);
        hv[4 * i + 3] = fmaxf(fmaf(v.w, s_bn[k0 + 3], s_bn[32 + k0 + 3]), 0.f);
    }
    u64 acc[16];
#pragma unroll
    for (int i = 0; i < 16; i++) acc[i] = 0ull;
    const ulonglong2* wb = (const ulonglong2*)s_w + q4 * 65;
#pragma unroll
    for (int k = 0; k < 8; k++) {
        u64 xp2 = pk2(hv[k], hv[k]);
        const ulonglong2* wr = wb + k * 8;
#pragma unroll
        for (int f = 0; f < 8; f++) {
            ulonglong2 wv = wr[f];
            ffma2(acc[2 * f], xp2, wv.x);
            ffma2(acc[2 * f + 1], xp2, wv.y);
        }
    }
#pragma unroll
    for (int f = 0; f < 16; f++) comb4(acc[f]);

    float a[32];
#pragma unroll
    for (int f = 0; f < 16; f++) upk2(acc[f], a[2 * f], a[2 * f + 1]);
#pragma unroll
    for (int f = 0; f < 32; f++) a[f] += s_b[f];

    if (q4 == 0) {
        float4* outp = (float4*)(g_A2 + (size_t)row * 32);
#pragma unroll
        for (int i = 0; i < 8; i++)
            outp[i] = make_float4(a[4 * i], a[4 * i + 1], a[4 * i + 2], a[4 * i + 3]);
    }

    int lane = tid & 31, warp = tid >> 5;
#pragma unroll
    for (int f = 0; f < 32; f++) {
        float sv = (q4 == 0) ? a[f] : 0.f;
        float qv = sv * a[f];
#pragma unroll
        for (int off = 16; off >= 1; off >>= 1) {
            sv += __shfl_xor_sync(0xffffffffu, sv, off);
            qv += __shfl_xor_sync(0xffffffffu, qv, off);
        }
        if (lane == 0) { s_red[warp * 64 + f] = sv; s_red[warp * 64 + 32 + f] = qv; }
    }
    __syncthreads();
    if (tid < 64) {
        float t = 0.f;
#pragma unroll
        for (int w = 0; w < 16; w++) t += s_red[w * 64 + tid];
        g_part2[blockIdx.x * 64 + tid] = t;
    }
}

// =====================================================================
// K3 (unchanged from R14 pass)
// =====================================================================
__global__ void k_mlp3(const float* __restrict__ W3, const float* __restrict__ b3,
                       const float* __restrict__ g2, const float* __restrict__ beta2)
{
    __shared__ float s_w[2064];
    __shared__ float s_bn[64];
    __shared__ float s_b[64];
    __shared__ float s_red[1024];
    int tid = threadIdx.x;
    for (int i = tid; i < 2048; i += 512) {
        int j = i >> 5, k = i & 31;
        int qq = k >> 3, kl = k & 7;
        s_w[qq * 516 + kl * 64 + j] = W3[i];
    }
    if (tid < 64) s_b[tid] = b3[tid];
    bn_finalize_partial(g_part2, s_red, tid);
    __syncthreads();
    bn_finalize_combine(s_red, g2, beta2, s_bn, tid);
    __syncthreads();

    int q4  = tid & 3;
    int row = blockIdx.x * 128 + (tid >> 2);
    int kb  = q4 * 8;

    float hv[8];
    const float4* ip = (const float4*)(g_A2 + (size_t)row * 32);
#pragma unroll
    for (int i = 0; i < 2; i++) {
        float4 v = ip[2 * q4 + i];
        int k0 = kb + 4 * i;
        hv[4 * i]     = fmaxf(fmaf(v.x, s_bn[k0],     s_bn[32 + k0]),     0.f);
        hv[4 * i + 1] = fmaxf(fmaf(v.y, s_bn[k0 + 1], s_bn[32 + k0 + 1]), 0.f);
        hv[4 * i + 2] = fmaxf(fmaf(v.z, s_bn[k0 + 2], s_bn[32 + k0 + 2]), 0.f);
        hv[4 * i + 3] = fmaxf(fmaf(v.w, s_bn[k0 + 3], s_bn[32 + k0 + 3]), 0.f);
    }
    u64 acc[32];
#pragma unroll
    for (int i = 0; i < 32; i++) acc[i] = 0ull;
    const ulonglong2* wb = (const ulonglong2*)s_w + q4 * 129;
#pragma unroll
    for (int k = 0; k < 8; k++) {
        u64 xp2 = pk2(hv[k], hv[k]);
        const ulonglong2* wr = wb + k * 16;
#pragma unroll
        for (int f = 0; f < 16; f++) {
            ulonglong2 wv = wr[f];
            ffma2(acc[2 * f], xp2, wv.x);
            ffma2(acc[2 * f + 1], xp2, wv.y);
        }
    }
#pragma unroll
    for (int f = 0; f < 32; f++) comb4(acc[f]);

    if (q4 == 0) {
        float4* outp = (float4*)(g_m + (size_t)row * 64);
#pragma unroll
        for (int i = 0; i < 16; i++) {
            float a, b, c, d;
            upk2(acc[2 * i], a, b);
            upk2(acc[2 * i + 1], c, d);
            outp[i] = make_float4(a + s_b[4 * i], b + s_b[4 * i + 1],
                                  c + s_b[4 * i + 2], d + s_b[4 * i + 3]);
        }
    }
}

// =====================================================================
// LSTM: shuffle-free gate layout + B-hi single-load. 128 x 512.
// =====================================================================
#define SW_OFF  0
#define SA0_OFF 65536
#define SC_OFF  131072
#define SBC_OFF 172032
#define SMEM_LSTM 173056

__device__ __forceinline__ void init_A(u8* smem, const float* __restrict__ gm,
                                       int s0, int tid)
{
    int row = tid >> 2, qtr = tid & 3;
    const float* src = gm + (size_t)(s0 + row) * 64 + qtr * 16;
    float v[16];
#pragma unroll
    for (int j = 0; j < 4; j++) {
        float4 t4 = *(const float4*)(src + 4 * j);
        v[4 * j] = t4.x; v[4 * j + 1] = t4.y; v[4 * j + 2] = t4.z; v[4 * j + 3] = t4.w;
    }
    int rowbase = SA0_OFF + row * 256;
    int kb = qtr * 32;
    int swz = (row & 7) << 4;
#pragma unroll
    for (int c4 = 0; c4 < 2; c4++) {
        uint4 hi4, lo4;
        u32* hp = (u32*)&hi4; u32* lp = (u32*)&lo4;
#pragma unroll
        for (int e = 0; e < 4; e++) {
            float a = v[c4 * 8 + 2 * e], b = v[c4 * 8 + 2 * e + 1];
            __nv_bfloat162 th = __floats2bfloat162_rn(a, b);
            float la = a - __bfloat162float(th.x);
            float lb = b - __bfloat162float(th.y);
            __nv_bfloat162 tl = __floats2bfloat162_rn(la, lb);
            hp[e] = *(u32*)&th;
            lp[e] = *(u32*)&tl;
        }
        int offh = rowbase + ((kb + c4 * 16) ^ swz);
        *(uint4*)(smem + offh)       = hi4;
        *(uint4*)(smem + offh + 128) = lo4;
    }
}

__global__ __launch_bounds__(512, 1)
void k_lstm_mma(const float* __restrict__ bih, const float* __restrict__ bhh,
                float* __restrict__ out)
{
    extern __shared__ u8 smem[];
    float* sCf  = (float*)(smem + SC_OFF);
    float* sBCf = (float*)(smem + SBC_OFF);

    int tid  = threadIdx.x;
    int wid  = tid >> 5;
    int lane = tid & 31;
    int s0   = blockIdx.x * 128;

    {
        uint4* d = (uint4*)(smem + SW_OFF);
        const uint4* s = (const uint4*)g_Wih_sw;
        for (int i = tid; i < 4096; i += 512) d[i] = s[i];
    }
    if (tid < 256) {
        int r = n_to_row(tid);
        sBCf[tid] = bih[r] + bhh[r];
    }
    for (int i = tid; i < 512 * 20; i += 512) sCf[i] = 0.f;
    init_A(smem, g_m, s0, tid);
    __syncthreads();

    int warp_m = wid & 1;
    int warp_n = wid >> 1;
    int lane8 = lane & 7;
    u32 sbase = smem_u32(smem);

    int rA = warp_m * 64 + lane8 + (lane & 8);
    int kA8b = (lane & 16) ? 16 : 0;
    int swzA = (rA & 7) << 4;
    u32 aRow = sbase + SA0_OFF + (u32)(rA * 256);

    int rB = warp_n * 32 + lane8 + ((lane & 16) >> 1);
    int kB8b = (lane & 8) ? 16 : 0;
    int swzB = (rB & 7) << 4;
    u32 bRow = sbase + SW_OFF + (u32)(rB * 256);

    int g    = lane >> 2;
    int L4   = lane & 3;
    int cbase = tid * 20;
    int barid = 1 + warp_m;

    // hoisted biases: bv[gate][e], col = warp_n*32 + gate*8 + 2*L4 + e
    float bv[4][2];
#pragma unroll
    for (int gt = 0; gt < 4; gt++) {
        int nc = warp_n * 32 + gt * 8 + 2 * L4;
        bv[gt][0] = sBCf[nc];
        bv[gt][1] = sBCf[nc + 1];
    }

    // epilogue constants
    int rowEa = warp_m * 64 + g;                       // row for mt=0, +8 for b-half
    u32 qb    = (u32)(16 * warp_n + 4 * L4);           // byte col in hi block
    u32 eoff  = qb ^ ((u32)g << 4);                    // swizzled (row&7 == g both rows)
    int qcol  = warp_n * 8 + 2 * L4;                   // output float col

#pragma unroll 1
    for (int t = 0; t < 26; t++) {
        u32 aBuf = aRow + ((t & 1) << 15);

        float acc[4][4][4];
#pragma unroll
        for (int mt = 0; mt < 4; mt++)
#pragma unroll
            for (int nt = 0; nt < 4; nt++)
#pragma unroll
                for (int e = 0; e < 4; e++) acc[mt][nt][e] = 0.f;

#pragma unroll
        for (int c = 0; c < 4; c++) {
            u32 afh[4][4], afl[4][4], bfh[2][4], bfl[2][4];
            u32 aoffh = (u32)((kA8b + 32 * c) ^ swzA);
            u32 aoffl = (u32)((kA8b + 32 * (c + 4)) ^ swzA);
            u32 boffh = (u32)((kB8b + 32 * c) ^ swzB);
            u32 boffl = (u32)((kB8b + 32 * (c + 4)) ^ swzB);
#pragma unroll
            for (int mt = 0; mt < 4; mt++)
                LDSM4(afh[mt][0], afh[mt][1], afh[mt][2], afh[mt][3],
                      aBuf + mt * 4096 + aoffh);
#pragma unroll
            for (int np = 0; np < 2; np++)
                LDSM4(bfh[np][0], bfh[np][1], bfh[np][2], bfh[np][3],
                      bRow + np * 4096 + boffh);
#pragma unroll
            for (int np = 0; np < 2; np++)
                LDSM4(bfl[np][0], bfl[np][1], bfl[np][2], bfl[np][3],
                      bRow + np * 4096 + boffl);
            // A_hi x B_hi
#pragma unroll
            for (int mt = 0; mt < 4; mt++)
#pragma unroll
                for (int np = 0; np < 2; np++) {
                    MMA16816(acc[mt][2 * np],     afh[mt][0], afh[mt][1], afh[mt][2], afh[mt][3],
                             bfh[np][0], bfh[np][1]);
                    MMA16816(acc[mt][2 * np + 1], afh[mt][0], afh[mt][1], afh[mt][2], afh[mt][3],
                             bfh[np][2], bfh[np][3]);
                }
            // A_hi x B_lo
#pragma unroll
            for (int mt = 0; mt < 4; mt++)
#pragma unroll
                for (int np = 0; np < 2; np++) {
                    MMA16816(acc[mt][2 * np],     afh[mt][0], afh[mt][1], afh[mt][2], afh[mt][3],
                             bfl[np][0], bfl[np][1]);
                    MMA16816(acc[mt][2 * np + 1], afh[mt][0], afh[mt][1], afh[mt][2], afh[mt][3],
                             bfl[np][2], bfl[np][3]);
                }
#pragma unroll
            for (int mt = 0; mt < 4; mt++)
                LDSM4(afl[mt][0], afl[mt][1], afl[mt][2], afl[mt][3],
                      aBuf + mt * 4096 + aoffl);
            // A_lo x B_hi
#pragma unroll
            for (int mt = 0; mt < 4; mt++)
#pragma unroll
                for (int np = 0; np < 2; np++) {
                    MMA16816(acc[mt][2 * np],     afl[mt][0], afl[mt][1], afl[mt][2], afl[mt][3],
                             bfh[np][0], bfh[np][1]);
                    MMA16816(acc[mt][2 * np + 1], afl[mt][0], afl[mt][1], afl[mt][2], afl[mt][3],
                             bfh[np][2], bfh[np][3]);
                }
        }

        // ---- shuffle-free epilogue ----
        u32 stBase = (u32)(SA0_OFF + (((t & 1) ^ 1) << 15)) + eoff;
#pragma unroll
        for (int mt = 0; mt < 4; mt++) {
            int rowA = rowEa + mt * 16;
            float4 cva = *(float4*)&sCf[cbase + mt * 4];
            float cc[4] = {cva.x, cva.y, cva.z, cva.w};
            float hres[4];
#pragma unroll
            for (int e = 0; e < 4; e++) {
                int eb = e & 1;
                float gi = acc[mt][0][e] + bv[0][eb];
                float gf = acc[mt][1][e] + bv[1][eb];
                float gg = acc[mt][2][e] + bv[2][eb];
                float go = acc[mt][3][e] + bv[3][eb];
                float si = fmaf(tanhfast(0.5f * gi), 0.5f, 0.5f);
                float sf = fmaf(tanhfast(0.5f * gf), 0.5f, 0.5f);
                float so = fmaf(tanhfast(0.5f * go), 0.5f, 0.5f);
                float tg = tanhfast(gg);
                float cn = fmaf(sf, cc[e], si * tg);
                cc[e] = cn;
                hres[e] = so * tanhfast(cn);
            }
            *(float4*)&sCf[cbase + mt * 4] = make_float4(cc[0], cc[1], cc[2], cc[3]);

            // pack pairs (q, q+1): e01 -> row A, e23 -> row A+8
            __nv_bfloat162 Ha = __floats2bfloat162_rn(hres[0], hres[1]);
            __nv_bfloat162 Hb = __floats2bfloat162_rn(hres[2], hres[3]);
            float la0 = hres[0] - __bfloat162float(Ha.x);
            float la1 = hres[1] - __bfloat162float(Ha.y);
            float lb0 = hres[2] - __bfloat162float(Hb.x);
            float lb1 = hres[3] - __bfloat162float(Hb.y);
            __nv_bfloat162 La = __floats2bfloat162_rn(la0, la1);
            __nv_bfloat162 Lb = __floats2bfloat162_rn(lb0, lb1);

            u32 addrA = stBase + (u32)(rowA * 256);
            u32 addrB = addrA + 2048;                  // +8 rows
            *(u32*)(smem + addrA)       = *(u32*)&Ha;
            *(u32*)(smem + addrA + 128) = *(u32*)&La;
            *(u32*)(smem + addrB)       = *(u32*)&Hb;
            *(u32*)(smem + addrB + 128) = *(u32*)&Lb;

            if (t >= 1) {
                size_t obase = ((size_t)(s0 + rowA) * NPRED + (t - 1)) * 64 + qcol;
                *(float2*)(out + obase) = make_float2(hres[0], hres[1]);
                *(float2*)(out + obase + (size_t)8 * NPRED * 64) = make_float2(hres[2], hres[3]);
            }
        }

        if (t == 0) {
            __syncthreads();
            uint4* d = (uint4*)(smem + SW_OFF);
            const uint4* src = (const uint4*)g_Wc_sw;
            for (int i = tid; i < 4096; i += 512) d[i] = src[i];
            __syncthreads();
        } else {
            BAR_HALF(barid);
        }
    }
}

// =====================================================================
extern "C" void kernel_launch(void* const* d_in, const int* in_sizes, int n_in,
                              void* d_out, int out_size)
{
    const float* x0    = (const float*)d_in[0];
    const float* x1    = (const float*)d_in[1];
    const float* x2    = (const float*)d_in[2];
    const float* W1    = (const float*)d_in[3];
    const float* b1    = (const float*)d_in[4];
    const float* g1    = (const float*)d_in[5];
    const float* beta1 = (const float*)d_in[6];
    const float* W2    = (const float*)d_in[7];
    const float* b2    = (const float*)d_in[8];
    const float* g2    = (const float*)d_in[9];
    const float* beta2 = (const float*)d_in[10];
    const float* W3    = (const float*)d_in[11];
    const float* b3    = (const float*)d_in[12];
    const float* Wih   = (const float*)d_in[13];
    const float* Whh   = (const float*)d_in[14];
    const float* bih   = (const float*)d_in[15];
    const float* bhh   = (const float*)d_in[16];
    float* out = (float*)d_out;

    cudaFuncSetAttribute(k_mlp1, cudaFuncAttributeMaxDynamicSharedMemorySize, 53440);
    cudaFuncSetAttribute(k_lstm_mma, cudaFuncAttributeMaxDynamicSharedMemorySize, SMEM_LSTM);

    k_mlp1<<<128, 512, 53440>>>(x0, x1, x2, W1, b1, Wih, Whh);
    k_mlp2<<<128, 512>>>(W2, b2, g1, beta1);
    k_mlp3<<<128, 512>>>(W3, b3, g2, beta2);
    k_lstm_mma<<<128, 512, SMEM_LSTM>>>(bih, bhh, out);
}